// round 7
// baseline (speedup 1.0000x reference)
#include <cuda_runtime.h>
#include <cuda_bf16.h>
#include <cstdint>

// ---------------------------------------------------------------------------
// SE3Convolution: build [52,52,5,5,5] filter from weights+bases, then
// dense 3D VALID conv  x[8,52,48,48,48] -> out[8,52,44,44,44]
// fp32 path: packed fma.rn.f32x2 (FFMA2), full-warp blocks (352 thr),
// double-buffered cp.async staging (weights + input) overlapped with compute.
// ---------------------------------------------------------------------------

#define NCH   52
#define DIN   48
#define DOUT  44
#define SS    5
#define TAPS  125
#define KB    4

#define CPG   13           // co per co-group (6 packed pairs + 1 scalar)
#define WPAD  64           // padded co-slots per tap: 4 groups x 16 floats

#define W_FLOATS   (TAPS * WPAD)          // 8000 floats = 32 KB per buffer
#define IN_FLOATS  (SS * 8 * DIN)         // 5*8*48 = 1920 floats = 7.68 KB
#define SMEM_FLOATS (2 * W_FLOATS + 2 * IN_FLOATS)
#define SMEM_BYTES  (SMEM_FLOATS * 4)     // 79,360 B

// Filter scratch in [ci][tap][WPAD] layout:
//   slot = (co/13)*16 + (co%13); slots 13..15 of each group zero-padded.
// Each co-group's 13 weights per tap are a 16B-aligned run: 12 load as
// 3x ld.shared.v2.u64 (pre-paired for FFMA2), 1 scalar.
__device__ __align__(16) float g_kernel[NCH * TAPS * WPAD];

// packed fp32x2 fma: acc = w * v + acc
#define FMA2(acc, w, v) \
    asm("fma.rn.f32x2 %0, %1, %2, %0;" : "+l"(acc) : "l"(w), "l"(v))

// 16B global->shared async copy (LDGSTS)
#define CP_ASYNC16(dst_u32, src_ptr) \
    asm volatile("cp.async.cg.shared.global [%0], [%1], 16;" \
                 :: "r"(dst_u32), "l"(src_ptr))

// ---------------------------------------------------------------------------
// Step 1: filter construction (one thread per [ci][tap][slot] element).
// ---------------------------------------------------------------------------
__global__ void build_filter_kernel(
    const float* __restrict__ w,
    const float* __restrict__ b00, const float* __restrict__ b01, const float* __restrict__ b02,
    const float* __restrict__ b10, const float* __restrict__ b11, const float* __restrict__ b12,
    const float* __restrict__ b20, const float* __restrict__ b21, const float* __restrict__ b22)
{
    int idx = blockIdx.x * blockDim.x + threadIdx.x;
    if (idx >= NCH * TAPS * WPAD) return;

    int slot = idx % WPAD;
    int tap  = (idx / WPAD) % TAPS;
    int ci   = idx / (WPAD * TAPS);

    int grp = slot >> 4, lane = slot & 15;
    if (lane >= CPG) { g_kernel[idx] = 0.f; return; }
    int co = grp * CPG + lane;         // 0..51

    // irreps: [0,8) l=0 (d=1,m=8); [8,32) l=1 (d=3,m=8); [32,52) l=2 (d=5,m=4)
    int i, ro;
    if      (co < 8)  { i = 0; ro = 0;  }
    else if (co < 32) { i = 1; ro = 8;  }
    else              { i = 2; ro = 32; }
    int j, rc;
    if      (ci < 8)  { j = 0; rc = 0;  }
    else if (ci < 32) { j = 1; rc = 8;  }
    else              { j = 2; rc = 32; }

    const int dims[3]  = {1, 3, 5};
    const int mults[3] = {8, 8, 4};
    const int woff[3][3] = {{0, 256, 512}, {640, 896, 1152}, {1280, 1408, 1536}};

    int d_o = dims[i], d_i = dims[j], m_i = mults[j];
    int u = (co - ro) / d_o, a = (co - ro) % d_o;
    int v = (ci - rc) / d_i, b = (ci - rc) % d_i;

    const float* B[9] = {b00, b01, b02, b10, b11, b12, b20, b21, b22};
    const float* bs = B[i * 3 + j];
    const float* wp = w + woff[i][j] + (u * m_i + v) * KB;

    float s = 0.f;
    #pragma unroll
    for (int k = 0; k < KB; k++)
        s += wp[k] * bs[((k * d_o + a) * d_i + b) * TAPS + tap];

    g_kernel[idx] = s;
}

// ---------------------------------------------------------------------------
// Step 2: direct 3D conv.
//
// Block (44,8) = 352 threads = 11 FULL warps.
// ty: co_grp = ty&3 (13 co), yh = ty>>2 (2 y-points). Thread: 13co x 2y.
// Block tile: 1 z x 4 y x 44 x x 52 co. Grid (44, 11, 8) = 3872 blocks.
// Double-buffered: prefetch ci+1 slabs (cp.async) during ci compute.
// ---------------------------------------------------------------------------
extern __shared__ __align__(16) float smem_dyn[];

__global__ void __launch_bounds__(352, 2) conv3d_kernel(
    const float* __restrict__ x, float* __restrict__ out)
{
    float* w_s  = smem_dyn;                    // 2 x 8000 floats
    float* in_s = smem_dyn + 2 * W_FLOATS;     // 2 x 1920 floats

    const int tx  = threadIdx.x;            // 0..43
    const int ty  = threadIdx.y;            // 0..7
    const int cg  = ty & 3;                 // co group
    const int y0  = (ty >> 2) * 2;          // 0 or 2 (first of 2 y-points)
    const int tid = ty * 44 + tx;           // 0..351
    const int zo  = blockIdx.x;             // 0..43
    const int yt  = blockIdx.y;             // 0..10
    const int n   = blockIdx.z;             // 0..7

    unsigned long long accp[6][2];          // 6 co-pairs x 2 y
    float accs[2];                          // 13th co x 2 y
    #pragma unroll
    for (int c = 0; c < 6; c++) { accp[c][0] = 0ull; accp[c][1] = 0ull; }
    accs[0] = 0.f; accs[1] = 0.f;

    const float* xn = x + (n * NCH) * (DIN * DIN * DIN);
    const uint32_t smem_base = (uint32_t)__cvta_generic_to_shared(smem_dyn);
    const uint32_t w_base_u  = smem_base;                       // w_s
    const uint32_t in_base_u = smem_base + 2 * W_FLOATS * 4;    // in_s

    // ---- prologue: issue loads for ci = 0 into buffer 0 ----
    {
        const float* xc = xn;                      // ci = 0
        for (int t = tid; t < 480; t += 352) {
            int x4  = (t % 12) * 4;
            int row = t / 12;
            int zz  = row >> 3, yy = row & 7;
            uint32_t dst = in_base_u + (uint32_t)(((zz * 8 + yy) * DIN + x4) * 4);
            CP_ASYNC16(dst, xc + ((zo + zz) * DIN + (yt * 4 + yy)) * DIN + x4);
        }
        const float* wg = g_kernel;                // ci = 0
        for (int t = tid; t < W_FLOATS / 4; t += 352)
            CP_ASYNC16(w_base_u + (uint32_t)(t * 16), wg + t * 4);
        asm volatile("cp.async.commit_group;");
    }

    #pragma unroll 1
    for (int ci = 0; ci < NCH; ci++) {
        const int cur = ci & 1;
        const uint32_t w_cur_u = w_base_u + (uint32_t)(cur * W_FLOATS * 4);
        const float* w_cur  = w_s  + cur * W_FLOATS;
        const float* in_cur = in_s + cur * IN_FLOATS;

        asm volatile("cp.async.wait_group 0;" ::: "memory");
        __syncthreads();   // current slabs visible; prev buffer's readers done

        // ---- prefetch ci+1 into the other buffer ----
        if (ci + 1 < NCH) {
            const int nxt = 1 - cur;
            const float* xc = xn + (ci + 1) * (DIN * DIN * DIN);
            const uint32_t in_nxt_u = in_base_u + (uint32_t)(nxt * IN_FLOATS * 4);
            for (int t = tid; t < 480; t += 352) {
                int x4  = (t % 12) * 4;
                int row = t / 12;
                int zz  = row >> 3, yy = row & 7;
                uint32_t dst = in_nxt_u + (uint32_t)(((zz * 8 + yy) * DIN + x4) * 4);
                CP_ASYNC16(dst, xc + ((zo + zz) * DIN + (yt * 4 + yy)) * DIN + x4);
            }
            const float* wg = g_kernel + (ci + 1) * W_FLOATS;
            const uint32_t w_nxt_u = w_base_u + (uint32_t)(nxt * W_FLOATS * 4);
            for (int t = tid; t < W_FLOATS / 4; t += 352)
                CP_ASYNC16(w_nxt_u + (uint32_t)(t * 16), wg + t * 4);
            asm volatile("cp.async.commit_group;");
        }

        // ---- compute from current buffers ----
        #pragma unroll 1
        for (int dz = 0; dz < SS; dz++) {
            #pragma unroll 1
            for (int dy = 0; dy < SS; dy++) {
                const float* row0 = in_cur + (dz * 8 + dy + y0) * DIN + tx;
                const int woff_f = (dz * SS + dy) * SS * WPAD + cg * 16;
                const uint32_t wrow_a = w_cur_u + (uint32_t)(woff_f * 4);
                const float* wrow = w_cur + woff_f;
                #pragma unroll
                for (int dx = 0; dx < SS; dx++) {
                    float v0 = row0[dx];
                    float v1 = row0[DIN + dx];

                    unsigned long long vp0, vp1;
                    asm("mov.b64 %0, {%1, %1};" : "=l"(vp0) : "f"(v0));
                    asm("mov.b64 %0, {%1, %1};" : "=l"(vp1) : "f"(v1));

                    uint32_t wa = wrow_a + (uint32_t)(dx * WPAD * 4);
                    unsigned long long wq[6];
                    asm volatile("ld.shared.v2.u64 {%0, %1}, [%2];"
                                 : "=l"(wq[0]), "=l"(wq[1]) : "r"(wa));
                    asm volatile("ld.shared.v2.u64 {%0, %1}, [%2+16];"
                                 : "=l"(wq[2]), "=l"(wq[3]) : "r"(wa));
                    asm volatile("ld.shared.v2.u64 {%0, %1}, [%2+32];"
                                 : "=l"(wq[4]), "=l"(wq[5]) : "r"(wa));
                    float w12 = wrow[dx * WPAD + 12];

                    #pragma unroll
                    for (int pp = 0; pp < 6; pp++) {
                        FMA2(accp[pp][0], wq[pp], vp0);
                        FMA2(accp[pp][1], wq[pp], vp1);
                    }
                    accs[0] = fmaf(w12, v0, accs[0]);
                    accs[1] = fmaf(w12, v1, accs[1]);
                }
            }
        }
    }

    // ---- epilogue: unpack pairs, coalesced over tx ----
    float* on = out + (n * NCH) * (DOUT * DOUT * DOUT);
    const int ybase = yt * 4 + y0;
    #pragma unroll
    for (int pp = 0; pp < 6; pp++) {
        int co0 = cg * CPG + 2 * pp;
        float* op0 = on + ((co0 * DOUT + zo) * DOUT + ybase) * DOUT + tx;
        float* op1 = op0 + DOUT * DOUT * DOUT;
        #pragma unroll
        for (int p = 0; p < 2; p++) {
            float lo, hi;
            asm("mov.b64 {%0, %1}, %2;" : "=f"(lo), "=f"(hi) : "l"(accp[pp][p]));
            op0[p * DOUT] = lo;
            op1[p * DOUT] = hi;
        }
    }
    {
        int co = cg * CPG + 12;
        float* op = on + ((co * DOUT + zo) * DOUT + ybase) * DOUT + tx;
        op[0]    = accs[0];
        op[DOUT] = accs[1];
    }
}

// ---------------------------------------------------------------------------
extern "C" void kernel_launch(void* const* d_in, const int* in_sizes, int n_in,
                              void* d_out, int out_size)
{
    const float* x = (const float*)d_in[0];
    const float* w = (const float*)d_in[1];

    build_filter_kernel<<<(NCH * TAPS * WPAD + 255) / 256, 256>>>(
        w,
        (const float*)d_in[2], (const float*)d_in[3], (const float*)d_in[4],
        (const float*)d_in[5], (const float*)d_in[6], (const float*)d_in[7],
        (const float*)d_in[8], (const float*)d_in[9], (const float*)d_in[10]);

    // Unconditional (idempotent) — no static guards per harness rules.
    cudaFuncSetAttribute(conv3d_kernel,
                         cudaFuncAttributeMaxDynamicSharedMemorySize,
                         SMEM_BYTES);

    dim3 grid(DOUT, 11, 8);   // (44, 11, 8)
    dim3 block(44, 8);        // 352 = 11 full warps
    conv3d_kernel<<<grid, block, SMEM_BYTES>>>(x, (float*)d_out);
}